// round 16
// baseline (speedup 1.0000x reference)
#include <cuda_runtime.h>
#include <cuda_bf16.h>
#include <cstdint>

#define Nn 50000
#define NnPad 50048
#define Ee 600000
#define Gg 512
#define NUM_TILES 391   // ceil(50000/128)

// ============================================================================
// PTX helpers: plain (non-'a') instructions only — ldmatrix / mma.sync / cp.async
// ============================================================================
__device__ __forceinline__ uint32_t smem_to_u32(const void* smem_ptr) {
    uint32_t addr;
    asm("{ .reg .u64 tmp; cvta.to.shared.u64 tmp, %1; cvt.u32.u64 %0, tmp; }"
        : "=r"(addr) : "l"(smem_ptr));
    return addr;
}

#define LDSM_X4(r0, r1, r2, r3, addr) \
    asm volatile("ldmatrix.sync.aligned.m8n8.x4.shared.b16 {%0,%1,%2,%3}, [%4];" \
        : "=r"(r0), "=r"(r1), "=r"(r2), "=r"(r3) : "r"(addr))

#define MMA16816(c, a0, a1, a2, a3, b0, b1) \
    asm volatile("mma.sync.aligned.m16n8k16.row.col.f32.bf16.bf16.f32 " \
        "{%0,%1,%2,%3}, {%4,%5,%6,%7}, {%8,%9}, {%0,%1,%2,%3};" \
        : "+f"((c)[0]), "+f"((c)[1]), "+f"((c)[2]), "+f"((c)[3]) \
        : "r"(a0), "r"(a1), "r"(a2), "r"(a3), "r"(b0), "r"(b1))

#define CP_ASYNC16(dst_u32, src_ptr) \
    asm volatile("cp.async.cg.shared.global [%0], [%1], 16;" \
        :: "r"(dst_u32), "l"(src_ptr) : "memory")
#define CP_COMMIT() asm volatile("cp.async.commit_group;" ::: "memory")
#define CP_WAIT2()  asm volatile("cp.async.wait_group 2;" ::: "memory")
#define CP_WAIT0()  asm volatile("cp.async.wait_group 0;" ::: "memory")

// ============================================================================
// Scratch (device globals) — single A buffer (in-place layer pipeline)
// ============================================================================
__device__ __align__(16) __nv_bfloat16 d_Ahi[(size_t)NnPad * 256];
__device__ __align__(16) __nv_bfloat16 d_Alo[(size_t)NnPad * 256];
__device__ __align__(16) __nv_bfloat16 d_Wh[3 * 128 * 256];
__device__ __align__(16) __nv_bfloat16 d_Wl[3 * 128 * 256];
__device__ __align__(16) float d_h[(size_t)NnPad * 128];
__device__ float d_pooled[Gg * 256];
__device__ int   d_csr[Ee];
__device__ int   d_rowptr[Nn + 1];
__device__ int   d_cursor[Nn];
__device__ int   d_degi[Nn];
__device__ int   d_gptr[Gg + 1];
__device__ int   d_is64;

// ============================================================================
// index dtype handling (int64 vs int32)
// ============================================================================
__device__ __forceinline__ int load_idx(const void* p, long long i, int is64) {
    if (is64) return (int)((const long long*)p)[i];
    return ((const int*)p)[i];
}

__device__ __forceinline__ int detect_is64_local(const void* __restrict__ ei) {
    const long long* p = (const long long*)ei;
    int ok = 1;
    #pragma unroll 4
    for (int i = 0; i < 64; ++i) {
        long long v = p[i];
        if (v < 0 || v >= (long long)Nn) { ok = 0; break; }
    }
    return ok;
}

// fused init: every block derives is64 locally; zero degi/cursor; gptr via
// boundary scan over the SORTED batch array (replaces 10.6us binary search).
__global__ void init_kernel(const void* __restrict__ ei,
                            const void* __restrict__ batch) {
    const int is64 = detect_is64_local(ei);
    if (blockIdx.x == 0 && threadIdx.x == 0) d_is64 = is64;

    int gid = blockIdx.x * blockDim.x + threadIdx.x;
    int stride = gridDim.x * blockDim.x;

    for (int j = gid; j < Nn; j += stride) { d_degi[j] = 0; d_cursor[j] = 0; }

    // boundary scan: gptr[g] = first index i with batch[i] >= g
    for (int i = gid; i < Nn; i += stride) {
        int b  = load_idx(batch, i, is64);
        int bp = (i > 0) ? load_idx(batch, i - 1, is64) : -1;
        for (int g = bp + 1; g <= b; ++g) d_gptr[g] = i;
        if (i == Nn - 1) {
            for (int g = b + 1; g <= Gg; ++g) d_gptr[g] = Nn;
        }
    }
}

__global__ void deg_hist_kernel(const void* __restrict__ ei) {
    int is64 = d_is64;
    int stride = gridDim.x * blockDim.x;
    for (int e = blockIdx.x * blockDim.x + threadIdx.x; e < Ee; e += stride) {
        int dst = load_idx(ei, (long long)Ee + e, is64);
        atomicAdd(&d_degi[dst], 1);
    }
}

// one-block exclusive scan: degi -> rowptr (+ cursor seed)
__global__ void scan_kernel() {
    __shared__ int sh[1024];
    const int SEG = 49;   // 1024*49 = 50176 >= 50001
    int t = threadIdx.x;
    int base = t * SEG;
    int s = 0;
    #pragma unroll 7
    for (int i = 0; i < SEG; ++i) {
        int idx = base + i;
        if (idx < Nn) s += d_degi[idx];
    }
    sh[t] = s;
    __syncthreads();
    for (int off = 1; off < 1024; off <<= 1) {
        int v = (t >= off) ? sh[t - off] : 0;
        __syncthreads();
        sh[t] += v;
        __syncthreads();
    }
    int run = t ? sh[t - 1] : 0;
    #pragma unroll 7
    for (int i = 0; i < SEG; ++i) {
        int idx = base + i;
        if (idx < Nn) { d_rowptr[idx] = run; d_cursor[idx] = run; run += d_degi[idx]; }
        else if (idx == Nn) { d_rowptr[Nn] = run; }
    }
}

__global__ void csr_fill_kernel(const void* __restrict__ ei) {
    int is64 = d_is64;
    int stride = gridDim.x * blockDim.x;
    for (int e = blockIdx.x * blockDim.x + threadIdx.x; e < Ee; e += stride) {
        int src = load_idx(ei, e, is64);
        int dst = load_idx(ei, (long long)Ee + e, is64);
        d_csr[atomicAdd(&d_cursor[dst], 1)] = src;
    }
}

// ============================================================================
// bf16 hi/lo split helpers
// ============================================================================
__device__ __forceinline__ void split_pack(float a, float b, uint32_t& hi, uint32_t& lo) {
    __nv_bfloat16 ha = __float2bfloat16_rn(a), hb = __float2bfloat16_rn(b);
    __nv_bfloat162 hv; hv.x = ha; hv.y = hb;
    hi = *reinterpret_cast<uint32_t*>(&hv);
    float la = a - __bfloat162float(ha);
    float lb = b - __bfloat162float(hb);
    __nv_bfloat162 lv = __floats2bfloat162_rn(la, lb);
    lo = *reinterpret_cast<uint32_t*>(&lv);
}

// fused weight prep (blocks 0..383) + x conversion (blocks 384..)
__global__ void prep_kernel(const float* __restrict__ x,
                            const float* W1l, const float* W1r,
                            const float* W2l, const float* W2r,
                            const float* W3l, const float* W3r) {
    if (blockIdx.x < 384) {
        int idx = blockIdx.x * blockDim.x + threadIdx.x;   // over 3*128*256
        int layer = idx / (128 * 256);
        int rem = idx - layer * 128 * 256;
        int o = rem >> 8, k = rem & 255;
        const float* Wl = layer == 0 ? W1l : layer == 1 ? W2l : W3l;
        const float* Wr = layer == 0 ? W1r : layer == 1 ? W2r : W3r;
        float v = (k < 128) ? Wl[o * 128 + k] : Wr[o * 128 + k - 128];
        __nv_bfloat16 hv = __float2bfloat16_rn(v);
        float lvf = v - __bfloat162float(hv);
        d_Wh[idx] = hv;
        d_Wl[idx] = __float2bfloat16_rn(lvf);
    } else {
        int idx = (blockIdx.x - 384) * blockDim.x + threadIdx.x;   // Nn*32
        if (idx >= Nn * 32) return;
        int n = idx >> 5, c4 = idx & 31;
        float4 v = *reinterpret_cast<const float4*>(x + (size_t)n * 128 + c4 * 4);
        uint32_t h0, l0, h1, l1;
        split_pack(v.x, v.y, h0, l0);
        split_pack(v.z, v.w, h1, l1);
        size_t off = (size_t)n * 256 + 128 + c4 * 4;
        uint2 hh; hh.x = h0; hh.y = h1;
        uint2 ll; ll.x = l0; ll.y = l1;
        *reinterpret_cast<uint2*>(&d_Ahi[off]) = hh;
        *reinterpret_cast<uint2*>(&d_Alo[off]) = ll;
    }
}

// ============================================================================
// mean aggregation: warp per node, cp.async-pipelined gather (R13-exact)
// ============================================================================
__global__ __launch_bounds__(256, 8) void agg_kernel(
    const float* __restrict__ x, int usex)
{
    __shared__ __align__(16) char buf[8][4][512];
    const float* __restrict__ src = usex ? x : d_h;
    const int warp = (blockIdx.x * blockDim.x + threadIdx.x) >> 5;   // exactly Nn warps
    const int wl = threadIdx.x >> 5;
    const int lane = threadIdx.x & 31;
    const int beg = d_rowptr[warp];
    const int end = d_rowptr[warp + 1];
    const uint32_t sbase = smem_to_u32(&buf[wl][0][0]) + lane * 16;

    float4 acc = make_float4(0.f, 0.f, 0.f, 0.f);
    int e = beg;
    #pragma unroll 1
    while (e < end) {
        const int n = (end - e) < 4 ? (end - e) : 4;
        #pragma unroll
        for (int d = 0; d < 4; ++d) {
            if (d < n) {
                int s = d_csr[e + d];
                CP_ASYNC16(sbase + d * 512,
                           reinterpret_cast<const char*>(src + (size_t)s * 128) + lane * 16);
            }
        }
        CP_COMMIT();
        CP_WAIT0();
        #pragma unroll
        for (int d = 0; d < 4; ++d) {
            if (d < n) {
                float4 v = *reinterpret_cast<const float4*>(&buf[wl][d][lane * 16]);
                acc.x += v.x; acc.y += v.y; acc.z += v.z; acc.w += v.w;
            }
        }
        e += n;
    }

    const int deg = end - beg;
    const float inv = 1.f / (float)(deg > 1 ? deg : 1);
    acc.x *= inv; acc.y *= inv; acc.z *= inv; acc.w *= inv;
    uint32_t h0, l0, h1, l1;
    split_pack(acc.x, acc.y, h0, l0);
    split_pack(acc.z, acc.w, h1, l1);
    size_t off = (size_t)warp * 256 + lane * 4;
    uint2 hh; hh.x = h0; hh.y = h1;
    uint2 ll; ll.x = l0; ll.y = l1;
    *reinterpret_cast<uint2*>(d_Ahi + off) = hh;
    *reinterpret_cast<uint2*>(d_Alo + off) = ll;
}

// ============================================================================
// Tensor-core GEMM via mma.sync — R13-EXACT (best known config, 326us):
// 512-thread CTA, 4x4 warp grid, 32x32 warp tiles, triple-buffered cp.async,
// in-place epilogue (each CTA overwrites cols 128..255 of its own rows).
// SMEM: Whi 64KB | Wlo 64KB | Abuf 3x16KB | bias 512B  = 180736 B
// ============================================================================
#define OFF_WHI  0
#define OFF_WLO  65536
#define OFF_A    131072
#define OFF_BIAS 180224
#define GEMM_SMEM 180736

__device__ __forceinline__ void prefetch_chunk512(const __nv_bfloat16* __restrict__ src,
                                                  size_t rowBase, int cbase,
                                                  uint32_t dst, int tid) {
    #pragma unroll
    for (int j = 0; j < 2; ++j) {
        int u = tid + j * 512;          // 0..1023 16B units
        int r = u >> 3, uu = u & 7;
        const __nv_bfloat16* s = src + (rowBase + r) * 256 + cbase + uu * 8;
        uint32_t d = dst + r * 128 + (((uu ^ (r & 7))) << 4);
        CP_ASYNC16(d, s);
    }
}

__global__ __launch_bounds__(512, 1)
void sage_mma_gemm(int layer, const float* __restrict__ bias,
                   int do_relu, int writeNext)
{
    extern __shared__ char smem[];
    const uint32_t sb = smem_to_u32(smem);
    const int tid = threadIdx.x;
    const int wid = tid >> 5, lane = tid & 31;
    const int wm = wid & 3, wn = wid >> 2;    // 4x4 warp grid

    const __nv_bfloat16* __restrict__ Ahi = d_Ahi;
    const __nv_bfloat16* __restrict__ Alo = d_Alo;
    const __nv_bfloat16* __restrict__ WhiG = d_Wh + layer * 32768;
    const __nv_bfloat16* __restrict__ WloG = d_Wl + layer * 32768;
    float* sbias = reinterpret_cast<float*>(smem + OFF_BIAS);

    // ---- load W (hi+lo) into swizzled SMEM: 4096 16B-units each ----
    #pragma unroll
    for (int m = 0; m < 2; ++m) {
        const __nv_bfloat16* srcW = m ? WloG : WhiG;
        char* dstW = smem + (m ? OFF_WLO : OFF_WHI);
        #pragma unroll 4
        for (int j = 0; j < 8; ++j) {
            int idx = tid + j * 512;     // 0..4095 16B units
            int n = idx >> 5, u = idx & 31;
            float4 v = *reinterpret_cast<const float4*>(srcW + n * 256 + u * 8);
            *reinterpret_cast<float4*>(dstW + n * 512 + ((u ^ (n & 7)) << 4)) = v;
        }
    }
    if (tid < 128) sbias[tid] = bias[tid];
    __syncthreads();

    const uint32_t sA = sb + OFF_A;

    for (int tile = blockIdx.x; tile < NUM_TILES; tile += gridDim.x) {
        const size_t rowBase = (size_t)tile * 128;

        float acc[32];
        #pragma unroll
        for (int i = 0; i < 32; ++i) acc[i] = 0.f;

        // chunk i: matrix = (i&1)?Alo:Ahi, k-base = (i>>1)*64, buf = i%3
        prefetch_chunk512(Ahi, rowBase, 0, sA, tid);                 // chunk 0 -> buf0
        CP_COMMIT();
        prefetch_chunk512(Alo, rowBase, 0, sA + 16384, tid);         // chunk 1 -> buf1
        CP_COMMIT();

        #pragma unroll 1
        for (int c = 0; c < 8; ++c) {
            {
                int cn = c + 2;
                if (cn < 8)
                    prefetch_chunk512((cn & 1) ? Alo : Ahi, rowBase, (cn >> 1) * 64,
                                      sA + (cn % 3) * 16384, tid);
                CP_COMMIT();   // one group per iteration (possibly empty)
            }
            CP_WAIT2();        // chunk c complete; chunks c+1, c+2 in flight
            __syncthreads();

            const uint32_t abuf = sA + (c % 3) * 16384;
            const int cbase = (c >> 1) * 64;
            const int nW = (c & 1) ? 1 : 2;   // hi chunk hits Whi+Wlo; lo chunk hits Whi

            #pragma unroll
            for (int ks = 0; ks < 4; ++ks) {
                uint32_t aa[2][4];
                #pragma unroll
                for (int mt = 0; mt < 2; ++mt) {
                    int r = wm * 32 + mt * 16 + (lane & 15);
                    int u = ks * 2 + (lane >> 4);
                    uint32_t ad = abuf + r * 128 + (((u ^ (r & 7))) << 4);
                    LDSM_X4(aa[mt][0], aa[mt][1], aa[mt][2], aa[mt][3], ad);
                }
                #pragma unroll
                for (int w2 = 0; w2 < 2; ++w2) {
                    if (w2 >= nW) break;
                    const uint32_t sW = sb + (w2 ? OFF_WLO : OFF_WHI);
                    #pragma unroll
                    for (int bt = 0; bt < 2; ++bt) {
                        int n = wn * 32 + bt * 16 + (lane & 15);
                        int kg = cbase + ks * 16 + ((lane >> 4) << 3);
                        int u = kg >> 3;
                        uint32_t bd = sW + n * 512 + (((u ^ (n & 7))) << 4);
                        uint32_t b0, b1, b2, b3;
                        LDSM_X4(b0, b1, b2, b3, bd);
                        #pragma unroll
                        for (int mt = 0; mt < 2; ++mt) {
                            MMA16816(&acc[(mt * 4 + bt * 2 + 0) * 4],
                                     aa[mt][0], aa[mt][1], aa[mt][2], aa[mt][3], b0, b2);
                            MMA16816(&acc[(mt * 4 + bt * 2 + 1) * 4],
                                     aa[mt][0], aa[mt][1], aa[mt][2], aa[mt][3], b1, b3);
                        }
                    }
                }
            }
            __syncthreads();
        }

        // ---- epilogue: bias + relu; fp32 h out + IN-PLACE bf16 split into
        //      A cols 128..255 of the SAME rows this CTA just consumed ----
        const int g = lane >> 2, tg = lane & 3;
        #pragma unroll
        for (int mt = 0; mt < 2; ++mt) {
            const int r0 = (int)rowBase + wm * 32 + mt * 16 + g;
            #pragma unroll
            for (int nt = 0; nt < 4; ++nt) {
                int col = wn * 32 + nt * 8 + tg * 2;
                float2 bb = *reinterpret_cast<const float2*>(&sbias[col]);
                int ai = (mt * 4 + nt) * 4;
                float v0 = acc[ai + 0] + bb.x;
                float v1 = acc[ai + 1] + bb.y;
                float v2 = acc[ai + 2] + bb.x;
                float v3 = acc[ai + 3] + bb.y;
                if (do_relu) {
                    v0 = fmaxf(v0, 0.f); v1 = fmaxf(v1, 0.f);
                    v2 = fmaxf(v2, 0.f); v3 = fmaxf(v3, 0.f);
                }
                if (r0 < Nn) {
                    float2 o; o.x = v0; o.y = v1;
                    *reinterpret_cast<float2*>(d_h + (size_t)r0 * 128 + col) = o;
                    if (writeNext) {
                        uint32_t hh, ll;
                        split_pack(v0, v1, hh, ll);
                        size_t off = (size_t)r0 * 256 + 128 + col;
                        *reinterpret_cast<uint32_t*>(d_Ahi + off) = hh;
                        *reinterpret_cast<uint32_t*>(d_Alo + off) = ll;
                    }
                }
                if (r0 + 8 < Nn) {
                    float2 o; o.x = v2; o.y = v3;
                    *reinterpret_cast<float2*>(d_h + (size_t)(r0 + 8) * 128 + col) = o;
                    if (writeNext) {
                        uint32_t hh, ll;
                        split_pack(v2, v3, hh, ll);
                        size_t off = (size_t)(r0 + 8) * 256 + 128 + col;
                        *reinterpret_cast<uint32_t*>(d_Ahi + off) = hh;
                        *reinterpret_cast<uint32_t*>(d_Alo + off) = ll;
                    }
                }
            }
        }
    }
}

// ============================================================================
// pooling (256 threads, 2-way row split halves the serial L2 chain) + head
// ============================================================================
__global__ __launch_bounds__(256) void pool_kernel() {
    __shared__ float s1[256], s2[256];
    int g = blockIdx.x;
    int c = threadIdx.x & 127, hf = threadIdx.x >> 7;
    int beg = d_gptr[g], end = d_gptr[g + 1];
    float mx = -3.402823466e38f, sm = 0.f;
    #pragma unroll 1
    for (int r = beg + hf; r < end; r += 2) {
        float v = d_h[(size_t)r * 128 + c];
        mx = fmaxf(mx, v);
        sm += v;
    }
    s1[threadIdx.x] = mx; s2[threadIdx.x] = sm;
    __syncthreads();
    if (hf == 0) {
        mx = fmaxf(mx, s1[c + 128]);
        sm += s2[c + 128];
        int cnt = end - beg;
        d_pooled[g * 256 + c]       = (cnt > 0) ? mx : 0.f;
        d_pooled[g * 256 + 128 + c] = sm / (float)(cnt > 1 ? cnt : 1);
    }
}

__global__ __launch_bounds__(256) void head_kernel(
    const float* __restrict__ Wlin, const float* __restrict__ blin,
    float* __restrict__ out)
{
    __shared__ float p[256];
    int g = blockIdx.x, o = threadIdx.x;
    p[o] = d_pooled[g * 256 + o];
    __syncthreads();
    float acc = blin[o];
    const float4* wr = reinterpret_cast<const float4*>(Wlin + o * 256);
    #pragma unroll 8
    for (int k = 0; k < 64; ++k) {
        float4 w = wr[k];
        float4 pv = *reinterpret_cast<const float4*>(&p[k * 4]);
        acc = fmaf(w.x, pv.x, acc);
        acc = fmaf(w.y, pv.y, acc);
        acc = fmaf(w.z, pv.z, acc);
        acc = fmaf(w.w, pv.w, acc);
    }
    out[g * 256 + o] = acc;
}

// ============================================================================
// launch — consolidated preproc (11 launches)
// ============================================================================
extern "C" void kernel_launch(void* const* d_in, const int* in_sizes, int n_in,
                              void* d_out, int out_size)
{
    const float* x     = (const float*)d_in[0];
    const void*  ei    = d_in[1];
    const void*  batch = d_in[2];
    const float* W1l = (const float*)d_in[3];
    const float* b1  = (const float*)d_in[4];
    const float* W1r = (const float*)d_in[5];
    const float* W2l = (const float*)d_in[6];
    const float* b2  = (const float*)d_in[7];
    const float* W2r = (const float*)d_in[8];
    const float* W3l = (const float*)d_in[9];
    const float* b3  = (const float*)d_in[10];
    const float* W3r = (const float*)d_in[11];
    const float* Wlin = (const float*)d_in[12];
    const float* blin = (const float*)d_in[13];
    float* out = (float*)d_out;

    cudaFuncSetAttribute(sage_mma_gemm, cudaFuncAttributeMaxDynamicSharedMemorySize, GEMM_SMEM);

    init_kernel<<<98, 512>>>(ei, batch);       // detect + zero + gptr boundary scan
    deg_hist_kernel<<<512, 256>>>(ei);
    scan_kernel<<<1, 1024>>>();                // rowptr + cursor seed
    csr_fill_kernel<<<512, 256>>>(ei);
    prep_kernel<<<6634, 256>>>(x, W1l, W1r, W2l, W2r, W3l, W3r);   // wprep + xconv

    const int aggBlocks = (Nn * 32 + 255) / 256;   // warp per node, exactly Nn warps

    // layer 1: agg(x) -> A cols 0..127; gemm reads A, writes h + A cols 128..255 in place
    agg_kernel<<<aggBlocks, 256>>>(x, 1);
    sage_mma_gemm<<<148, 512, GEMM_SMEM>>>(0, b1, 1, 1);
    // layer 2
    agg_kernel<<<aggBlocks, 256>>>(nullptr, 0);
    sage_mma_gemm<<<148, 512, GEMM_SMEM>>>(1, b2, 1, 1);
    // layer 3 (no relu, no writeNext)
    agg_kernel<<<aggBlocks, 256>>>(nullptr, 0);
    sage_mma_gemm<<<148, 512, GEMM_SMEM>>>(2, b3, 0, 0);

    pool_kernel<<<Gg, 256>>>();
    head_kernel<<<Gg, 256>>>(Wlin, blin, out);
}

// round 17
// speedup vs baseline: 1.1416x; 1.1416x over previous
#include <cuda_runtime.h>
#include <cuda_bf16.h>
#include <cstdint>

#define Nn 50000
#define NnPad 50048
#define Ee 600000
#define Gg 512
#define NUM_TILES 391   // ceil(50000/128)

// ============================================================================
// PTX helpers: plain (non-'a') instructions only — ldmatrix / mma.sync / cp.async
// ============================================================================
__device__ __forceinline__ uint32_t smem_to_u32(const void* smem_ptr) {
    uint32_t addr;
    asm("{ .reg .u64 tmp; cvta.to.shared.u64 tmp, %1; cvt.u32.u64 %0, tmp; }"
        : "=r"(addr) : "l"(smem_ptr));
    return addr;
}

#define LDSM_X4(r0, r1, r2, r3, addr) \
    asm volatile("ldmatrix.sync.aligned.m8n8.x4.shared.b16 {%0,%1,%2,%3}, [%4];" \
        : "=r"(r0), "=r"(r1), "=r"(r2), "=r"(r3) : "r"(addr))

#define MMA16816(c, a0, a1, a2, a3, b0, b1) \
    asm volatile("mma.sync.aligned.m16n8k16.row.col.f32.bf16.bf16.f32 " \
        "{%0,%1,%2,%3}, {%4,%5,%6,%7}, {%8,%9}, {%0,%1,%2,%3};" \
        : "+f"((c)[0]), "+f"((c)[1]), "+f"((c)[2]), "+f"((c)[3]) \
        : "r"(a0), "r"(a1), "r"(a2), "r"(a3), "r"(b0), "r"(b1))

#define CP_ASYNC16(dst_u32, src_ptr) \
    asm volatile("cp.async.cg.shared.global [%0], [%1], 16;" \
        :: "r"(dst_u32), "l"(src_ptr) : "memory")
#define CP_COMMIT() asm volatile("cp.async.commit_group;" ::: "memory")
#define CP_WAIT2()  asm volatile("cp.async.wait_group 2;" ::: "memory")
#define CP_WAIT0()  asm volatile("cp.async.wait_group 0;" ::: "memory")

// ============================================================================
// Scratch (device globals) — single A buffer (in-place layer pipeline)
// ============================================================================
__device__ __align__(16) __nv_bfloat16 d_Ahi[(size_t)NnPad * 256];
__device__ __align__(16) __nv_bfloat16 d_Alo[(size_t)NnPad * 256];
__device__ __align__(16) __nv_bfloat16 d_Wh[3 * 128 * 256];
__device__ __align__(16) __nv_bfloat16 d_Wl[3 * 128 * 256];
__device__ __align__(16) float d_h[(size_t)NnPad * 128];
__device__ float d_pooled[Gg * 256];
__device__ int   d_csr[Ee];
__device__ int   d_rowptr[Nn + 1];
__device__ int   d_cursor[Nn];
__device__ int   d_degi[Nn];
__device__ int   d_gptr[Gg + 1];
__device__ int   d_is64;

// ============================================================================
// index dtype handling (int64 vs int32)
// ============================================================================
__device__ __forceinline__ int load_idx(const void* p, long long i, int is64) {
    if (is64) return (int)((const long long*)p)[i];
    return ((const int*)p)[i];
}
__global__ void detect_kernel(const void* __restrict__ ei) {
    const long long* p = (const long long*)ei;
    int ok = 1;
    for (int i = 0; i < 64; ++i) {
        long long v = p[i];
        if (v < 0 || v >= (long long)Nn) { ok = 0; break; }
    }
    d_is64 = ok;
}

// gptr via grid-wide boundary scan over the SORTED batch array
// (replaces the 10.6us single-block binary search; ~0.8MB coalesced reads)
__global__ void gptr_kernel(const void* __restrict__ batch) {
    int is64 = d_is64;
    int gid = blockIdx.x * blockDim.x + threadIdx.x;
    int stride = gridDim.x * blockDim.x;
    for (int i = gid; i < Nn; i += stride) {
        int b  = load_idx(batch, i, is64);
        int bp = (i > 0) ? load_idx(batch, i - 1, is64) : -1;
        for (int g = bp + 1; g <= b; ++g) d_gptr[g] = i;
        if (i == Nn - 1) {
            for (int g = b + 1; g <= Gg; ++g) d_gptr[g] = Nn;
        }
    }
}

__global__ void zero_kernel() {
    int i = blockIdx.x * blockDim.x + threadIdx.x;
    int stride = gridDim.x * blockDim.x;
    for (int j = i; j < Nn; j += stride) { d_degi[j] = 0; d_cursor[j] = 0; }
}

__global__ void deg_hist_kernel(const void* __restrict__ ei) {
    int is64 = d_is64;
    int stride = gridDim.x * blockDim.x;
    for (int e = blockIdx.x * blockDim.x + threadIdx.x; e < Ee; e += stride) {
        int dst = load_idx(ei, (long long)Ee + e, is64);
        atomicAdd(&d_degi[dst], 1);
    }
}

// one-block exclusive scan: degi -> rowptr
__global__ void scan_kernel() {
    __shared__ int sh[1024];
    const int SEG = 49;   // 1024*49 = 50176 >= 50001
    int t = threadIdx.x;
    int base = t * SEG;
    int s = 0;
    #pragma unroll 7
    for (int i = 0; i < SEG; ++i) {
        int idx = base + i;
        if (idx < Nn) s += d_degi[idx];
    }
    sh[t] = s;
    __syncthreads();
    for (int off = 1; off < 1024; off <<= 1) {
        int v = (t >= off) ? sh[t - off] : 0;
        __syncthreads();
        sh[t] += v;
        __syncthreads();
    }
    int run = t ? sh[t - 1] : 0;
    #pragma unroll 7
    for (int i = 0; i < SEG; ++i) {
        int idx = base + i;
        if (idx < Nn) { d_rowptr[idx] = run; run += d_degi[idx]; }
        else if (idx == Nn) { d_rowptr[Nn] = run; }
    }
}

__global__ void csr_fill_kernel(const void* __restrict__ ei) {
    int is64 = d_is64;
    int stride = gridDim.x * blockDim.x;
    for (int e = blockIdx.x * blockDim.x + threadIdx.x; e < Ee; e += stride) {
        int src = load_idx(ei, e, is64);
        int dst = load_idx(ei, (long long)Ee + e, is64);
        int pos = d_rowptr[dst] + atomicAdd(&d_cursor[dst], 1);
        d_csr[pos] = src;
    }
}

// ============================================================================
// bf16 hi/lo split helpers
// ============================================================================
__device__ __forceinline__ void split_pack(float a, float b, uint32_t& hi, uint32_t& lo) {
    __nv_bfloat16 ha = __float2bfloat16_rn(a), hb = __float2bfloat16_rn(b);
    __nv_bfloat162 hv; hv.x = ha; hv.y = hb;
    hi = *reinterpret_cast<uint32_t*>(&hv);
    float la = a - __bfloat162float(ha);
    float lb = b - __bfloat162float(hb);
    __nv_bfloat162 lv = __floats2bfloat162_rn(la, lb);
    lo = *reinterpret_cast<uint32_t*>(&lv);
}

// convert weights: Wcat[layer][o][k] = k<128 ? Wl[o][k] : Wr[o][k-128], split hi/lo
__global__ void wprep_kernel(const float* W1l, const float* W1r,
                             const float* W2l, const float* W2r,
                             const float* W3l, const float* W3r) {
    int idx = blockIdx.x * blockDim.x + threadIdx.x;   // over 3*128*256
    if (idx >= 3 * 128 * 256) return;
    int layer = idx / (128 * 256);
    int rem = idx - layer * 128 * 256;
    int o = rem >> 8, k = rem & 255;
    const float* Wl = layer == 0 ? W1l : layer == 1 ? W2l : W3l;
    const float* Wr = layer == 0 ? W1r : layer == 1 ? W2r : W3r;
    float v = (k < 128) ? Wl[o * 128 + k] : Wr[o * 128 + k - 128];
    __nv_bfloat16 hv = __float2bfloat16_rn(v);
    float lvf = v - __bfloat162float(hv);
    d_Wh[idx] = hv;
    d_Wl[idx] = __float2bfloat16_rn(lvf);
}

// convert x into A cols 128..255 (self features for layer 1)
__global__ void xconv_kernel(const float* __restrict__ x) {
    int idx = blockIdx.x * blockDim.x + threadIdx.x;   // Nn*32
    if (idx >= Nn * 32) return;
    int n = idx >> 5, c4 = idx & 31;
    float4 v = *reinterpret_cast<const float4*>(x + (size_t)n * 128 + c4 * 4);
    uint32_t h0, l0, h1, l1;
    split_pack(v.x, v.y, h0, l0);
    split_pack(v.z, v.w, h1, l1);
    size_t off = (size_t)n * 256 + 128 + c4 * 4;
    uint2 hh; hh.x = h0; hh.y = h1;
    uint2 ll; ll.x = l0; ll.y = l1;
    *reinterpret_cast<uint2*>(&d_Ahi[off]) = hh;
    *reinterpret_cast<uint2*>(&d_Alo[off]) = ll;
}

// ============================================================================
// mean aggregation: warp per node, cp.async-pipelined gather (R13-exact)
// ============================================================================
__global__ __launch_bounds__(256, 8) void agg_kernel(
    const float* __restrict__ x, int usex)
{
    __shared__ __align__(16) char buf[8][4][512];
    const float* __restrict__ src = usex ? x : d_h;
    const int warp = (blockIdx.x * blockDim.x + threadIdx.x) >> 5;   // exactly Nn warps
    const int wl = threadIdx.x >> 5;
    const int lane = threadIdx.x & 31;
    const int beg = d_rowptr[warp];
    const int end = d_rowptr[warp + 1];
    const uint32_t sbase = smem_to_u32(&buf[wl][0][0]) + lane * 16;

    float4 acc = make_float4(0.f, 0.f, 0.f, 0.f);
    int e = beg;
    #pragma unroll 1
    while (e < end) {
        const int n = (end - e) < 4 ? (end - e) : 4;
        #pragma unroll
        for (int d = 0; d < 4; ++d) {
            if (d < n) {
                int s = d_csr[e + d];
                CP_ASYNC16(sbase + d * 512,
                           reinterpret_cast<const char*>(src + (size_t)s * 128) + lane * 16);
            }
        }
        CP_COMMIT();
        CP_WAIT0();
        #pragma unroll
        for (int d = 0; d < 4; ++d) {
            if (d < n) {
                float4 v = *reinterpret_cast<const float4*>(&buf[wl][d][lane * 16]);
                acc.x += v.x; acc.y += v.y; acc.z += v.z; acc.w += v.w;
            }
        }
        e += n;
    }

    const int deg = end - beg;
    const float inv = 1.f / (float)(deg > 1 ? deg : 1);
    acc.x *= inv; acc.y *= inv; acc.z *= inv; acc.w *= inv;
    uint32_t h0, l0, h1, l1;
    split_pack(acc.x, acc.y, h0, l0);
    split_pack(acc.z, acc.w, h1, l1);
    size_t off = (size_t)warp * 256 + lane * 4;
    uint2 hh; hh.x = h0; hh.y = h1;
    uint2 ll; ll.x = l0; ll.y = l1;
    *reinterpret_cast<uint2*>(d_Ahi + off) = hh;
    *reinterpret_cast<uint2*>(d_Alo + off) = ll;
}

// ============================================================================
// Tensor-core GEMM via mma.sync — R13-EXACT (best known config, 326us):
// 512-thread CTA, 4x4 warp grid, 32x32 warp tiles, triple-buffered cp.async,
// in-place epilogue (each CTA overwrites cols 128..255 of its own rows).
// SMEM: Whi 64KB | Wlo 64KB | Abuf 3x16KB | bias 512B  = 180736 B
// ============================================================================
#define OFF_WHI  0
#define OFF_WLO  65536
#define OFF_A    131072
#define OFF_BIAS 180224
#define GEMM_SMEM 180736

__device__ __forceinline__ void prefetch_chunk512(const __nv_bfloat16* __restrict__ src,
                                                  size_t rowBase, int cbase,
                                                  uint32_t dst, int tid) {
    #pragma unroll
    for (int j = 0; j < 2; ++j) {
        int u = tid + j * 512;          // 0..1023 16B units
        int r = u >> 3, uu = u & 7;
        const __nv_bfloat16* s = src + (rowBase + r) * 256 + cbase + uu * 8;
        uint32_t d = dst + r * 128 + (((uu ^ (r & 7))) << 4);
        CP_ASYNC16(d, s);
    }
}

__global__ __launch_bounds__(512, 1)
void sage_mma_gemm(int layer, const float* __restrict__ bias,
                   int do_relu, int writeNext)
{
    extern __shared__ char smem[];
    const uint32_t sb = smem_to_u32(smem);
    const int tid = threadIdx.x;
    const int wid = tid >> 5, lane = tid & 31;
    const int wm = wid & 3, wn = wid >> 2;    // 4x4 warp grid

    const __nv_bfloat16* __restrict__ Ahi = d_Ahi;
    const __nv_bfloat16* __restrict__ Alo = d_Alo;
    const __nv_bfloat16* __restrict__ WhiG = d_Wh + layer * 32768;
    const __nv_bfloat16* __restrict__ WloG = d_Wl + layer * 32768;
    float* sbias = reinterpret_cast<float*>(smem + OFF_BIAS);

    // ---- load W (hi+lo) into swizzled SMEM: 4096 16B-units each ----
    #pragma unroll
    for (int m = 0; m < 2; ++m) {
        const __nv_bfloat16* srcW = m ? WloG : WhiG;
        char* dstW = smem + (m ? OFF_WLO : OFF_WHI);
        #pragma unroll 4
        for (int j = 0; j < 8; ++j) {
            int idx = tid + j * 512;     // 0..4095 16B units
            int n = idx >> 5, u = idx & 31;
            float4 v = *reinterpret_cast<const float4*>(srcW + n * 256 + u * 8);
            *reinterpret_cast<float4*>(dstW + n * 512 + ((u ^ (n & 7)) << 4)) = v;
        }
    }
    if (tid < 128) sbias[tid] = bias[tid];
    __syncthreads();

    const uint32_t sA = sb + OFF_A;

    for (int tile = blockIdx.x; tile < NUM_TILES; tile += gridDim.x) {
        const size_t rowBase = (size_t)tile * 128;

        float acc[32];
        #pragma unroll
        for (int i = 0; i < 32; ++i) acc[i] = 0.f;

        // chunk i: matrix = (i&1)?Alo:Ahi, k-base = (i>>1)*64, buf = i%3
        prefetch_chunk512(Ahi, rowBase, 0, sA, tid);                 // chunk 0 -> buf0
        CP_COMMIT();
        prefetch_chunk512(Alo, rowBase, 0, sA + 16384, tid);         // chunk 1 -> buf1
        CP_COMMIT();

        #pragma unroll 1
        for (int c = 0; c < 8; ++c) {
            {
                int cn = c + 2;
                if (cn < 8)
                    prefetch_chunk512((cn & 1) ? Alo : Ahi, rowBase, (cn >> 1) * 64,
                                      sA + (cn % 3) * 16384, tid);
                CP_COMMIT();   // one group per iteration (possibly empty)
            }
            CP_WAIT2();        // chunk c complete; chunks c+1, c+2 in flight
            __syncthreads();

            const uint32_t abuf = sA + (c % 3) * 16384;
            const int cbase = (c >> 1) * 64;
            const int nW = (c & 1) ? 1 : 2;   // hi chunk hits Whi+Wlo; lo chunk hits Whi

            #pragma unroll
            for (int ks = 0; ks < 4; ++ks) {
                uint32_t aa[2][4];
                #pragma unroll
                for (int mt = 0; mt < 2; ++mt) {
                    int r = wm * 32 + mt * 16 + (lane & 15);
                    int u = ks * 2 + (lane >> 4);
                    uint32_t ad = abuf + r * 128 + (((u ^ (r & 7))) << 4);
                    LDSM_X4(aa[mt][0], aa[mt][1], aa[mt][2], aa[mt][3], ad);
                }
                #pragma unroll
                for (int w2 = 0; w2 < 2; ++w2) {
                    if (w2 >= nW) break;
                    const uint32_t sW = sb + (w2 ? OFF_WLO : OFF_WHI);
                    #pragma unroll
                    for (int bt = 0; bt < 2; ++bt) {
                        int n = wn * 32 + bt * 16 + (lane & 15);
                        int kg = cbase + ks * 16 + ((lane >> 4) << 3);
                        int u = kg >> 3;
                        uint32_t bd = sW + n * 512 + (((u ^ (n & 7))) << 4);
                        uint32_t b0, b1, b2, b3;
                        LDSM_X4(b0, b1, b2, b3, bd);
                        #pragma unroll
                        for (int mt = 0; mt < 2; ++mt) {
                            MMA16816(&acc[(mt * 4 + bt * 2 + 0) * 4],
                                     aa[mt][0], aa[mt][1], aa[mt][2], aa[mt][3], b0, b2);
                            MMA16816(&acc[(mt * 4 + bt * 2 + 1) * 4],
                                     aa[mt][0], aa[mt][1], aa[mt][2], aa[mt][3], b1, b3);
                        }
                    }
                }
            }
            __syncthreads();
        }

        // ---- epilogue: bias + relu; fp32 h out + IN-PLACE bf16 split into
        //      A cols 128..255 of the SAME rows this CTA just consumed ----
        const int g = lane >> 2, tg = lane & 3;
        #pragma unroll
        for (int mt = 0; mt < 2; ++mt) {
            const int r0 = (int)rowBase + wm * 32 + mt * 16 + g;
            #pragma unroll
            for (int nt = 0; nt < 4; ++nt) {
                int col = wn * 32 + nt * 8 + tg * 2;
                float2 bb = *reinterpret_cast<const float2*>(&sbias[col]);
                int ai = (mt * 4 + nt) * 4;
                float v0 = acc[ai + 0] + bb.x;
                float v1 = acc[ai + 1] + bb.y;
                float v2 = acc[ai + 2] + bb.x;
                float v3 = acc[ai + 3] + bb.y;
                if (do_relu) {
                    v0 = fmaxf(v0, 0.f); v1 = fmaxf(v1, 0.f);
                    v2 = fmaxf(v2, 0.f); v3 = fmaxf(v3, 0.f);
                }
                if (r0 < Nn) {
                    float2 o; o.x = v0; o.y = v1;
                    *reinterpret_cast<float2*>(d_h + (size_t)r0 * 128 + col) = o;
                    if (writeNext) {
                        uint32_t hh, ll;
                        split_pack(v0, v1, hh, ll);
                        size_t off = (size_t)r0 * 256 + 128 + col;
                        *reinterpret_cast<uint32_t*>(d_Ahi + off) = hh;
                        *reinterpret_cast<uint32_t*>(d_Alo + off) = ll;
                    }
                }
                if (r0 + 8 < Nn) {
                    float2 o; o.x = v2; o.y = v3;
                    *reinterpret_cast<float2*>(d_h + (size_t)(r0 + 8) * 128 + col) = o;
                    if (writeNext) {
                        uint32_t hh, ll;
                        split_pack(v2, v3, hh, ll);
                        size_t off = (size_t)(r0 + 8) * 256 + 128 + col;
                        *reinterpret_cast<uint32_t*>(d_Ahi + off) = hh;
                        *reinterpret_cast<uint32_t*>(d_Alo + off) = ll;
                    }
                }
            }
        }
    }
}

// ============================================================================
// pooling + head — R13-exact
// ============================================================================
__global__ void pool_kernel() {
    int g = blockIdx.x;
    int c = threadIdx.x;              // 128 threads, one per column
    int beg = d_gptr[g], end = d_gptr[g + 1];
    float mx = -3.402823466e38f, sm = 0.f;
    for (int r = beg; r < end; ++r) {
        float v = d_h[(size_t)r * 128 + c];
        mx = fmaxf(mx, v);
        sm += v;
    }
    int cnt = end - beg;
    d_pooled[g * 256 + c]       = (cnt > 0) ? mx : 0.f;
    d_pooled[g * 256 + 128 + c] = sm / (float)(cnt > 1 ? cnt : 1);
}

__global__ __launch_bounds__(256) void head_kernel(
    const float* __restrict__ Wlin, const float* __restrict__ blin,
    float* __restrict__ out)
{
    __shared__ float p[256];
    int g = blockIdx.x, o = threadIdx.x;
    p[o] = d_pooled[g * 256 + o];
    __syncthreads();
    float acc = blin[o];
    const float4* wr = reinterpret_cast<const float4*>(Wlin + o * 256);
    #pragma unroll 8
    for (int k = 0; k < 64; ++k) {
        float4 w = wr[k];
        float4 pv = *reinterpret_cast<const float4*>(&p[k * 4]);
        acc = fmaf(w.x, pv.x, acc);
        acc = fmaf(w.y, pv.y, acc);
        acc = fmaf(w.z, pv.z, acc);
        acc = fmaf(w.w, pv.w, acc);
    }
    out[g * 256 + o] = acc;
}

// ============================================================================
// launch — R13-exact sequence; only gptr body changed (boundary scan)
// ============================================================================
extern "C" void kernel_launch(void* const* d_in, const int* in_sizes, int n_in,
                              void* d_out, int out_size)
{
    const float* x     = (const float*)d_in[0];
    const void*  ei    = d_in[1];
    const void*  batch = d_in[2];
    const float* W1l = (const float*)d_in[3];
    const float* b1  = (const float*)d_in[4];
    const float* W1r = (const float*)d_in[5];
    const float* W2l = (const float*)d_in[6];
    const float* b2  = (const float*)d_in[7];
    const float* W2r = (const float*)d_in[8];
    const float* W3l = (const float*)d_in[9];
    const float* b3  = (const float*)d_in[10];
    const float* W3r = (const float*)d_in[11];
    const float* Wlin = (const float*)d_in[12];
    const float* blin = (const float*)d_in[13];
    float* out = (float*)d_out;

    cudaFuncSetAttribute(sage_mma_gemm, cudaFuncAttributeMaxDynamicSharedMemorySize, GEMM_SMEM);

    detect_kernel<<<1, 1>>>(ei);
    gptr_kernel<<<98, 512>>>(batch);           // boundary scan (was 1-block binary search)
    zero_kernel<<<98, 512>>>();
    deg_hist_kernel<<<512, 256>>>(ei);
    scan_kernel<<<1, 1024>>>();
    csr_fill_kernel<<<512, 256>>>(ei);

    wprep_kernel<<<384, 256>>>(W1l, W1r, W2l, W2r, W3l, W3r);
    xconv_kernel<<<6250, 256>>>(x);

    const int aggBlocks = (Nn * 32 + 255) / 256;   // warp per node, exactly Nn warps

    // layer 1: agg(x) -> A cols 0..127; gemm reads A, writes h + A cols 128..255 in place
    agg_kernel<<<aggBlocks, 256>>>(x, 1);
    sage_mma_gemm<<<148, 512, GEMM_SMEM>>>(0, b1, 1, 1);
    // layer 2
    agg_kernel<<<aggBlocks, 256>>>(nullptr, 0);
    sage_mma_gemm<<<148, 512, GEMM_SMEM>>>(1, b2, 1, 1);
    // layer 3 (no relu, no writeNext)
    agg_kernel<<<aggBlocks, 256>>>(nullptr, 0);
    sage_mma_gemm<<<148, 512, GEMM_SMEM>>>(2, b3, 0, 0);

    pool_kernel<<<Gg, 128>>>();
    head_kernel<<<Gg, 256>>>(Wlin, blin, out);
}